// round 2
// baseline (speedup 1.0000x reference)
#include <cuda_runtime.h>
#include <math.h>

#define NN 25000
#define EE 400000
#define TOTE (EE + NN)
#define HD 384
#define DH 128

// ---------------- device scratch (no allocations allowed) ----------------
__device__ __align__(16) float g_xl[NN * HD];
__device__ __align__(16) float g_xr[NN * HD];
__device__ __align__(16) float g_xin[NN * HD];
__device__ __align__(16) float g_h2[NN * HD];
__device__ __align__(16) float g_h[NN * DH];
__device__ __align__(16) float g_y[NN * DH];
__device__ int   g_deg[NN];
__device__ int   g_rowptr[NN + 1];
__device__ int   g_fill[NN];
__device__ int   g_srcs[TOTE];
__device__ float g_bnsum[DH];
__device__ float g_bnsq[DH];

// ---------------- small helpers ----------------
__device__ __forceinline__ float4 f4add(float4 a, float4 b) {
    return make_float4(a.x + b.x, a.y + b.y, a.z + b.z, a.w + b.w);
}
__device__ __forceinline__ float4 f4scale(float4 a, float s) {
    return make_float4(a.x * s, a.y * s, a.z * s, a.w * s);
}
__device__ __forceinline__ float4 f4fma(float4 a, float s, float4 c) {
    return make_float4(fmaf(a.x, s, c.x), fmaf(a.y, s, c.y),
                       fmaf(a.z, s, c.z), fmaf(a.w, s, c.w));
}
__device__ __forceinline__ float4 f4lrelu(float4 v) {
    const float ns = 0.2f;
    return make_float4(v.x > 0.f ? v.x : ns * v.x,
                       v.y > 0.f ? v.y : ns * v.y,
                       v.z > 0.f ? v.z : ns * v.z,
                       v.w > 0.f ? v.w : ns * v.w);
}
__device__ __forceinline__ float f4dot(float4 a, float4 b) {
    return fmaf(a.x, b.x, fmaf(a.y, b.y, fmaf(a.z, b.z, a.w * b.w)));
}

// ---------------- CSR build ----------------
__global__ void set_int_kernel(int* p, int n, int v) {
    int i = blockIdx.x * blockDim.x + threadIdx.x;
    if (i < n) p[i] = v;
}

__global__ void hist_kernel(const int* __restrict__ ei, int* __restrict__ deg) {
    int i = blockIdx.x * blockDim.x + threadIdx.x;
    if (i < EE) {
        int d = ei[EE + i];
        if (d >= 0 && d < NN) atomicAdd(&deg[d], 1);
    }
}

__global__ void scan_kernel(const int* __restrict__ deg, int* __restrict__ rowptr,
                            int* __restrict__ fill) {
    __shared__ int sh[1024];
    const int CH = 25;  // 1024*25 >= 25000
    int t = threadIdx.x;
    int start = t * CH;
    int end = start + CH;
    if (start > NN) start = NN;
    if (end > NN) end = NN;
    int s = 0;
    for (int i = start; i < end; i++) s += deg[i];
    sh[t] = s;
    __syncthreads();
    for (int o = 1; o < 1024; o <<= 1) {
        int v = (t >= o) ? sh[t - o] : 0;
        __syncthreads();
        sh[t] += v;
        __syncthreads();
    }
    int off = (t == 0) ? 0 : sh[t - 1];
    for (int i = start; i < end; i++) {
        rowptr[i] = off;
        fill[i] = off;
        off += deg[i];
    }
    if (t == 1023) rowptr[NN] = sh[1023];
}

__global__ void scatter_kernel(const int* __restrict__ ei, int* __restrict__ fill,
                               int* __restrict__ srcs) {
    int i = blockIdx.x * blockDim.x + threadIdx.x;
    if (i >= TOTE) return;
    int s, d;
    if (i < EE) {
        s = ei[i];
        d = ei[EE + i];
    } else {
        s = d = i - EE;  // self loop
    }
    if (s < 0 || s >= NN || d < 0 || d >= NN) return;
    int pos = atomicAdd(&fill[d], 1);
    srcs[pos] = s;
}

// ---------------- GEMM: C[M,N] = A[M,K] @ B[K,N] (+bias) (+=C if accum) ----------------
// BM=128, BN=64, BK=16, 256 threads, 8x4 per thread.
__global__ void __launch_bounds__(256) gemm_kernel(const float* __restrict__ A,
                                                   const float* __restrict__ B,
                                                   const float* __restrict__ bias,
                                                   float* __restrict__ C, int M, int N,
                                                   int K, int accum) {
    __shared__ float As[16][128];
    __shared__ float Bs[16][64];
    int tid = threadIdx.x;
    int bm = blockIdx.y * 128;
    int bn = blockIdx.x * 64;
    int tx = tid & 15;  // n: 16*4
    int ty = tid >> 4;  // m: 16*8

    float acc[8][4];
#pragma unroll
    for (int i = 0; i < 8; i++)
#pragma unroll
        for (int j = 0; j < 4; j++) acc[i][j] = 0.f;

    for (int k0 = 0; k0 < K; k0 += 16) {
        // Load A tile 128x16 (two float4 per thread)
#pragma unroll
        for (int l = 0; l < 2; l++) {
            int f = tid + l * 256;       // float4 id in [0,512)
            int r = f >> 2;              // row in tile
            int kc = (f & 3) << 2;       // k within tile
            int grow = bm + r;
            float4 v = make_float4(0.f, 0.f, 0.f, 0.f);
            if (grow < M) v = *(const float4*)(A + (size_t)grow * K + k0 + kc);
            As[kc + 0][r] = v.x;
            As[kc + 1][r] = v.y;
            As[kc + 2][r] = v.z;
            As[kc + 3][r] = v.w;
        }
        // Load B tile 16x64 (one float4 per thread)
        {
            int r = tid >> 4;
            int nc = (tid & 15) << 2;
            float4 v = *(const float4*)(B + (size_t)(k0 + r) * N + bn + nc);
            *(float4*)&Bs[r][nc] = v;
        }
        __syncthreads();
#pragma unroll
        for (int kk = 0; kk < 16; kk++) {
            float4 av0 = *(const float4*)&As[kk][ty * 8];
            float4 av1 = *(const float4*)&As[kk][ty * 8 + 4];
            float4 bv = *(const float4*)&Bs[kk][tx * 4];
            float ra[8] = {av0.x, av0.y, av0.z, av0.w, av1.x, av1.y, av1.z, av1.w};
            float rb[4] = {bv.x, bv.y, bv.z, bv.w};
#pragma unroll
            for (int i = 0; i < 8; i++)
#pragma unroll
                for (int j = 0; j < 4; j++) acc[i][j] = fmaf(ra[i], rb[j], acc[i][j]);
        }
        __syncthreads();
    }

#pragma unroll
    for (int i = 0; i < 8; i++) {
        int row = bm + ty * 8 + i;
        if (row >= M) continue;
#pragma unroll
        for (int j = 0; j < 4; j++) {
            int col = bn + tx * 4 + j;
            float v = acc[i][j];
            if (bias) v += bias[col];
            if (accum) v += C[(size_t)row * N + col];
            C[(size_t)row * N + col] = v;
        }
    }
}

// ---------------- GATv2 attention: one warp per dst node, online softmax ----------------
__global__ void attn_kernel(const float* __restrict__ xl, const float* __restrict__ xr,
                            const float* __restrict__ att, const float* __restrict__ bias,
                            const int* __restrict__ rowptr, const int* __restrict__ srcs,
                            float* __restrict__ out) {
    int w = (blockIdx.x * blockDim.x + threadIdx.x) >> 5;
    if (w >= NN) return;
    int lane = threadIdx.x & 31;
    const float4* xl4 = (const float4*)xl;
    const float4* xr4 = (const float4*)xr;
    const float4* at4 = (const float4*)att;
    const float4* b4 = (const float4*)bias;

    size_t rb = (size_t)w * 96 + lane;
    float4 r0 = xr4[rb], r1 = xr4[rb + 32], r2 = xr4[rb + 64];
    float4 a0 = at4[lane], a1 = at4[32 + lane], a2 = at4[64 + lane];

    float4 acc0 = make_float4(0, 0, 0, 0), acc1 = acc0, acc2 = acc0;
    float den0 = 0.f, den1 = 0.f, den2 = 0.f;
    float m0 = -1e30f, m1 = -1e30f, m2 = -1e30f;

    int beg = rowptr[w], end = rowptr[w + 1];
    for (int e = beg; e < end; e++) {
        int s = srcs[e];
        const float4* p = xl4 + (size_t)s * 96 + lane;
        float4 x0 = p[0], x1 = p[32], x2 = p[64];
        float s0 = f4dot(a0, f4lrelu(f4add(x0, r0)));
        float s1 = f4dot(a1, f4lrelu(f4add(x1, r1)));
        float s2 = f4dot(a2, f4lrelu(f4add(x2, r2)));
#pragma unroll
        for (int o = 16; o; o >>= 1) {
            s0 += __shfl_xor_sync(0xffffffffu, s0, o);
            s1 += __shfl_xor_sync(0xffffffffu, s1, o);
            s2 += __shfl_xor_sync(0xffffffffu, s2, o);
        }
        if (s0 > m0) { float c = __expf(m0 - s0); acc0 = f4scale(acc0, c); den0 *= c; m0 = s0; }
        if (s1 > m1) { float c = __expf(m1 - s1); acc1 = f4scale(acc1, c); den1 *= c; m1 = s1; }
        if (s2 > m2) { float c = __expf(m2 - s2); acc2 = f4scale(acc2, c); den2 *= c; m2 = s2; }
        float w0 = __expf(s0 - m0);
        float w1 = __expf(s1 - m1);
        float w2 = __expf(s2 - m2);
        acc0 = f4fma(x0, w0, acc0); den0 += w0;
        acc1 = f4fma(x1, w1, acc1); den1 += w1;
        acc2 = f4fma(x2, w2, acc2); den2 += w2;
    }
    float4* o4 = (float4*)out;
    o4[rb]      = f4add(f4scale(acc0, 1.0f / den0), b4[lane]);
    o4[rb + 32] = f4add(f4scale(acc1, 1.0f / den1), b4[32 + lane]);
    o4[rb + 64] = f4add(f4scale(acc2, 1.0f / den2), b4[64 + lane]);
}

// ---------------- BatchNorm ----------------
__global__ void bn_zero_kernel(float* s, float* q) {
    int i = threadIdx.x;
    if (i < DH) s[i] = 0.f;
    else if (i < 2 * DH) q[i - DH] = 0.f;
}

__global__ void bn_stats_kernel(const float* __restrict__ x, float* __restrict__ sum,
                                float* __restrict__ sq) {
    int col = threadIdx.x;  // 128 threads
    float s = 0.f, q = 0.f;
    for (int r = blockIdx.x; r < NN; r += gridDim.x) {
        float v = x[(size_t)r * DH + col];
        s += v;
        q = fmaf(v, v, q);
    }
    atomicAdd(&sum[col], s);
    atomicAdd(&sq[col], q);
}

__global__ void bn_apply_kernel(const float* __restrict__ x, const float* __restrict__ sum,
                                const float* __restrict__ sq, const float* __restrict__ g,
                                const float* __restrict__ be, float* __restrict__ out) {
    int i = blockIdx.x * blockDim.x + threadIdx.x;
    if (i >= NN * DH) return;
    int col = i & (DH - 1);
    const float invN = 1.0f / (float)NN;
    float mu = sum[col] * invN;
    float var = sq[col] * invN - mu * mu;
    float v = g[col] * (x[i] - mu) * rsqrtf(var + 1e-5f) + be[col];
    out[i] = v > 0.f ? v : 0.f;
}

// ---------------- host ----------------
static void* symaddr(const void* sym) {
    void* p = nullptr;
    cudaGetSymbolAddress(&p, sym);
    return p;
}

extern "C" void kernel_launch(void* const* d_in, const int* in_sizes, int n_in,
                              void* d_out, int out_size) {
    const float* x       = (const float*)d_in[0];
    const int* ei        = (const int*)d_in[1];   // int32: JAX canonicalizes int64->int32
    const float* Wl1 = (const float*)d_in[2];
    const float* bl1 = (const float*)d_in[3];
    const float* Wr1 = (const float*)d_in[4];
    const float* br1 = (const float*)d_in[5];
    const float* att1 = (const float*)d_in[6];
    const float* bc1 = (const float*)d_in[7];
    const float* g1 = (const float*)d_in[8];
    const float* be1 = (const float*)d_in[9];
    const float* Wl2 = (const float*)d_in[10];
    const float* bl2 = (const float*)d_in[11];
    const float* Wr2 = (const float*)d_in[12];
    const float* br2 = (const float*)d_in[13];
    const float* att2 = (const float*)d_in[14];
    const float* bc2 = (const float*)d_in[15];
    const float* g2 = (const float*)d_in[16];
    const float* be2 = (const float*)d_in[17];
    const float* W1 = (const float*)d_in[18];
    const float* b1 = (const float*)d_in[19];
    const float* W2 = (const float*)d_in[20];
    const float* b2 = (const float*)d_in[21];
    float* out = (float*)d_out;

    float* xl    = (float*)symaddr(g_xl);
    float* xr    = (float*)symaddr(g_xr);
    float* xin   = (float*)symaddr(g_xin);
    float* h2    = (float*)symaddr(g_h2);
    float* h     = (float*)symaddr(g_h);
    float* y     = (float*)symaddr(g_y);
    int* deg     = (int*)symaddr(g_deg);
    int* rowptr  = (int*)symaddr(g_rowptr);
    int* fill    = (int*)symaddr(g_fill);
    int* srcs    = (int*)symaddr(g_srcs);
    float* bnsum = (float*)symaddr(g_bnsum);
    float* bnsq  = (float*)symaddr(g_bnsq);

    // ---- CSR build (deg starts at 1 for the self loop) ----
    set_int_kernel<<<(NN + 255) / 256, 256>>>(deg, NN, 1);
    hist_kernel<<<(EE + 255) / 256, 256>>>(ei, deg);
    scan_kernel<<<1, 1024>>>(deg, rowptr, fill);
    scatter_kernel<<<(TOTE + 255) / 256, 256>>>(ei, fill, srcs);

    dim3 g384(HD / 64, (NN + 127) / 128);
    dim3 g128(DH / 64, (NN + 127) / 128);
    int attn_blocks = (NN * 32 + 255) / 256;

    // ---- Layer 1 ----
    gemm_kernel<<<g384, 256>>>(x, Wl1, bl1, xl, NN, HD, DH, 0);
    gemm_kernel<<<g384, 256>>>(x, Wr1, br1, xr, NN, HD, DH, 0);
    attn_kernel<<<attn_blocks, 256>>>(xl, xr, att1, bc1, rowptr, srcs, xin);
    gemm_kernel<<<g128, 256>>>(xin, W1, b1, y, NN, DH, HD, 0);
    bn_zero_kernel<<<1, 256>>>(bnsum, bnsq);
    bn_stats_kernel<<<256, DH>>>(y, bnsum, bnsq);
    bn_apply_kernel<<<(NN * DH + 255) / 256, 256>>>(y, bnsum, bnsq, g1, be1, h);

    // ---- Layer 2 ----
    gemm_kernel<<<g384, 256>>>(h, Wl2, bl2, xl, NN, HD, DH, 0);
    gemm_kernel<<<g384, 256>>>(h, Wr2, br2, xr, NN, HD, DH, 0);
    attn_kernel<<<attn_blocks, 256>>>(xl, xr, att2, bc2, rowptr, srcs, h2);
    // concat GEMM: y = h2 @ W2[0:384] + xin @ W2[384:768] + b2
    gemm_kernel<<<g128, 256>>>(h2, W2, b2, y, NN, DH, HD, 0);
    gemm_kernel<<<g128, 256>>>(xin, W2 + (size_t)HD * DH, nullptr, y, NN, DH, HD, 1);
    bn_zero_kernel<<<1, 256>>>(bnsum, bnsq);
    bn_stats_kernel<<<256, DH>>>(y, bnsum, bnsq);
    bn_apply_kernel<<<(NN * DH + 255) / 256, 256>>>(y, bnsum, bnsq, g2, be2, out);
}